// round 17
// baseline (speedup 1.0000x reference)
#include <cuda_runtime.h>
#include <cuda_bf16.h>
#include <math.h>

// SimilarityLoss: out = mean(pos) + mean(clip(MARGIN - kth-smallest-dist, 0))
//   norms    : fused init + full sq norms + positive loss + builds bf16
//              augmented screen vectors over dims [0,30):
//                a~ = [-2*a0..-2*a29, 1, 0]   b~ = [b0..b29, |b|^2_30, 0]
//              so dot(a~,b~) = -2*dot_30 + s2p30, and
//                d2_30 = s1p30 + dot(a~,b~)  (lower bound of true d2_64)
//   screen   : bf16 tensor-core GEMM (mma.sync m16n8k16) 8192x8192xK32;
//              per-row min of d2_30; atomicMin on ordered-uint bits
//   compact  : list of rows with min d2_30 < 8.0 (expected: none; bf16 error
//              << 4.0 slack to the exact 4.0 boundary)
//   exact    : flagged rows only, fp32 64-dim top-quant with jax-top_k
//              tie-breaking; reads flag count once, exits if 0
//   finalize : deterministic fixed-order reduction -> scalar

#define NROWS 8192
#define DDIM  64
#define KS    32           // augmented screen K (30 data dims + norm + pad)
#define TR    128
#define TC    128
#define NCTA_COL 2
#define COLS_PER (NROWS / NCTA_COL)
#define NTILES   (COLS_PER / TC)
#define SPITCH   40        // smem row pitch in bf16 (conflict-free ldmatrix)
#define THRESH   8.0f
#define MARGIN_V 2.0f

__device__ float g_sq1[NROWS];
__device__ float g_sq2[NROWS];
__device__ float g_sq1p[NROWS];   // partial norm over dims [0,30)
__device__ float g_pos[NROWS];
__device__ float g_neg[NROWS];
__device__ unsigned int g_mind2[NROWS];
__device__ int g_flagged[NROWS];
__device__ int g_nflag;
__device__ __nv_bfloat16 g_abf[NROWS * KS];
__device__ __nv_bfloat16 g_bbf[NROWS * KS];
__device__ unsigned long long g_scratch[64][NROWS];

// ---------------------------------------------------------------- norms + init + bf16
__global__ void norms_kernel(const float* __restrict__ o1,
                             const float* __restrict__ o2) {
    int warp = threadIdx.x >> 5;
    int lane = threadIdx.x & 31;
    int row = blockIdx.x * 8 + warp;
    if (row >= NROWS) return;
    if (threadIdx.x == 0 && blockIdx.x == 0) g_nflag = 0;
    const float* a = o1 + row * DDIM;
    const float* b = o2 + row * DDIM;
    float a0 = a[lane], a1 = a[lane + 32];
    float b0 = b[lane], b1 = b[lane + 32];
    float s1p = (lane < 30) ? a0 * a0 : 0.0f;
    float s2p = (lane < 30) ? b0 * b0 : 0.0f;
    float s1 = a0 * a0 + a1 * a1;
    float s2 = b0 * b0 + b1 * b1;
    float d0 = b0 - a0, d1 = b1 - a1;
    float pp = d0 * d0 + d1 * d1;
    #pragma unroll
    for (int off = 16; off > 0; off >>= 1) {
        s1  += __shfl_xor_sync(0xffffffffu, s1,  off);
        s2  += __shfl_xor_sync(0xffffffffu, s2,  off);
        s1p += __shfl_xor_sync(0xffffffffu, s1p, off);
        s2p += __shfl_xor_sync(0xffffffffu, s2p, off);
        pp  += __shfl_xor_sync(0xffffffffu, pp,  off);
    }
    // augmented bf16 vectors (all lanes have the reduced s2p)
    __nv_bfloat16 av, bv;
    if (lane < 30) {
        av = __float2bfloat16(-2.0f * a0);
        bv = __float2bfloat16(b0);
    } else if (lane == 30) {
        av = __float2bfloat16(1.0f);
        bv = __float2bfloat16(s2p);
    } else {
        av = __float2bfloat16(0.0f);
        bv = __float2bfloat16(0.0f);
    }
    g_abf[row * KS + lane] = av;
    g_bbf[row * KS + lane] = bv;
    if (lane == 0) {
        g_sq1[row] = s1;
        g_sq2[row] = s2;
        g_sq1p[row] = s1p;
        g_pos[row] = pp;
        g_neg[row] = 0.0f;
        g_mind2[row] = 0x7F800000u;  // +inf
    }
}

// ---------------------------------------------------------------- screen (tensor core)
// grid (64, 2), block 256 (8 warps as 4(m) x 2(n)). Tile 128x128, K=32.
// Each warp: 32 rows x 64 cols = 2 m-atoms x 8 n-atoms of m16n8k16 bf16 mma.
__global__ void __launch_bounds__(256, 1)
screen_kernel() {
    __shared__ __align__(16) __nv_bfloat16 As[TR * SPITCH];
    __shared__ __align__(16) __nv_bfloat16 Bs[TC * SPITCH];

    int tid = threadIdx.x;
    int lane = tid & 31;
    int w = tid >> 5;
    int mw = w & 3;           // m group: rows mw*32..+31
    int nw = w >> 2;          // n group: cols nw*64..+63
    int row0 = blockIdx.x * TR;
    int cb = blockIdx.y;

    unsigned int as_u = (unsigned int)__cvta_generic_to_shared(As);
    unsigned int bs_u = (unsigned int)__cvta_generic_to_shared(Bs);

    // precompute ldmatrix lane addresses (tile-invariant)
    int lg = lane >> 3, li = lane & 7;
    // A frags: [matom][kchunk]
    unsigned int aaddr[2][2];
    #pragma unroll
    for (int ma = 0; ma < 2; ma++)
        #pragma unroll
        for (int ka = 0; ka < 2; ka++) {
            int r = mw * 32 + ma * 16 + (lg & 1) * 8 + li;
            int c = ka * 16 + (lg >> 1) * 8;
            aaddr[ma][ka] = as_u + (r * SPITCH + c) * 2;
        }
    // B frags: [npair][kchunk], x4 covers n-atoms (2*np, 2*np+1)
    unsigned int baddr[4][2];
    #pragma unroll
    for (int np = 0; np < 4; np++)
        #pragma unroll
        for (int ka = 0; ka < 2; ka++) {
            int n = nw * 64 + np * 16 + (lg >> 1) * 8 + li;
            int c = ka * 16 + (lg & 1) * 8;
            baddr[np][ka] = bs_u + (n * SPITCH + c) * 2;
        }

    // A tile load (once): thread t -> row t/2, half t%2; half = 16 bf16 = 32B
    {
        int r = tid >> 1, h = tid & 1;
        const uint4* src = (const uint4*)(g_abf + (row0 + r) * KS + h * 16);
        uint4 v0 = src[0], v1 = src[1];
        uint4* dst = (uint4*)(As + r * SPITCH + h * 16);
        dst[0] = v0;
        dst[1] = v1;
    }

    float minv[4];
    #pragma unroll
    for (int s = 0; s < 4; s++) minv[s] = 1e30f;

    // B prefetch (tile 0): same 32B-per-thread scheme
    int pr = tid >> 1, ph = tid & 1;
    uint4 pv0, pv1;
    {
        const uint4* src = (const uint4*)(g_bbf + (cb * COLS_PER + pr) * KS + ph * 16);
        pv0 = src[0];
        pv1 = src[1];
    }

    for (int ct = 0; ct < NTILES; ct++) {
        __syncthreads();
        {
            uint4* dst = (uint4*)(Bs + pr * SPITCH + ph * 16);
            dst[0] = pv0;
            dst[1] = pv1;
        }
        __syncthreads();
        if (ct + 1 < NTILES) {
            const uint4* src = (const uint4*)
                (g_bbf + (cb * COLS_PER + (ct + 1) * TC + pr) * KS + ph * 16);
            pv0 = src[0];
            pv1 = src[1];
        }

        // load fragments
        unsigned int af[2][2][4];
        #pragma unroll
        for (int ma = 0; ma < 2; ma++)
            #pragma unroll
            for (int ka = 0; ka < 2; ka++)
                asm volatile("ldmatrix.sync.aligned.m8n8.x4.shared.b16 {%0,%1,%2,%3}, [%4];"
                    : "=r"(af[ma][ka][0]), "=r"(af[ma][ka][1]),
                      "=r"(af[ma][ka][2]), "=r"(af[ma][ka][3])
                    : "r"(aaddr[ma][ka]));
        unsigned int bf[2][8][2];  // [kchunk][natom][2]
        #pragma unroll
        for (int np = 0; np < 4; np++)
            #pragma unroll
            for (int ka = 0; ka < 2; ka++) {
                unsigned int r0, r1, r2, r3;
                asm volatile("ldmatrix.sync.aligned.m8n8.x4.shared.b16 {%0,%1,%2,%3}, [%4];"
                    : "=r"(r0), "=r"(r1), "=r"(r2), "=r"(r3)
                    : "r"(baddr[np][ka]));
                bf[ka][2 * np][0] = r0;  bf[ka][2 * np][1] = r1;
                bf[ka][2 * np + 1][0] = r2;  bf[ka][2 * np + 1][1] = r3;
            }

        float acc[2][8][4];
        #pragma unroll
        for (int ma = 0; ma < 2; ma++)
            #pragma unroll
            for (int na = 0; na < 8; na++)
                asm volatile(
                    "mma.sync.aligned.m16n8k16.row.col.f32.bf16.bf16.f32 "
                    "{%0,%1,%2,%3}, {%4,%5,%6,%7}, {%8,%9}, {%10,%11,%12,%13};"
                    : "=f"(acc[ma][na][0]), "=f"(acc[ma][na][1]),
                      "=f"(acc[ma][na][2]), "=f"(acc[ma][na][3])
                    : "r"(af[ma][0][0]), "r"(af[ma][0][1]),
                      "r"(af[ma][0][2]), "r"(af[ma][0][3]),
                      "r"(bf[0][na][0]), "r"(bf[0][na][1]),
                      "f"(0.0f), "f"(0.0f), "f"(0.0f), "f"(0.0f));
        #pragma unroll
        for (int ma = 0; ma < 2; ma++)
            #pragma unroll
            for (int na = 0; na < 8; na++)
                asm volatile(
                    "mma.sync.aligned.m16n8k16.row.col.f32.bf16.bf16.f32 "
                    "{%0,%1,%2,%3}, {%4,%5,%6,%7}, {%8,%9}, {%10,%11,%12,%13};"
                    : "=f"(acc[ma][na][0]), "=f"(acc[ma][na][1]),
                      "=f"(acc[ma][na][2]), "=f"(acc[ma][na][3])
                    : "r"(af[ma][1][0]), "r"(af[ma][1][1]),
                      "r"(af[ma][1][2]), "r"(af[ma][1][3]),
                      "r"(bf[1][na][0]), "r"(bf[1][na][1]),
                      "f"(acc[ma][na][0]), "f"(acc[ma][na][1]),
                      "f"(acc[ma][na][2]), "f"(acc[ma][na][3]));

        // epilogue: acc holds (-2*dot + s2p); min per row-slot
        #pragma unroll
        for (int ma = 0; ma < 2; ma++) {
            float m0 = acc[ma][0][0], m1 = acc[ma][0][2];
            m0 = fminf(m0, acc[ma][0][1]);
            m1 = fminf(m1, acc[ma][0][3]);
            #pragma unroll
            for (int na = 1; na < 8; na++) {
                m0 = fminf(m0, fminf(acc[ma][na][0], acc[ma][na][1]));
                m1 = fminf(m1, fminf(acc[ma][na][2], acc[ma][na][3]));
            }
            minv[ma * 2 + 0] = fminf(minv[ma * 2 + 0], m0);
            minv[ma * 2 + 1] = fminf(minv[ma * 2 + 1], m1);
        }
    }

    // reduce across the 4 threads sharing each row (lane%4 = col phase)
    #pragma unroll
    for (int s = 0; s < 4; s++) {
        minv[s] = fminf(minv[s], __shfl_xor_sync(0xffffffffu, minv[s], 1));
        minv[s] = fminf(minv[s], __shfl_xor_sync(0xffffffffu, minv[s], 2));
    }
    if ((lane & 3) == 0) {
        #pragma unroll
        for (int s = 0; s < 4; s++) {
            int row = mw * 32 + (s >> 1) * 16 + (s & 1) * 8 + (lane >> 2);
            float m = g_sq1p[row0 + row] + minv[s];  // d2_30 lower bound
            m = fmaxf(m, 0.0f);
            atomicMin(&g_mind2[row0 + row], __float_as_uint(m));
        }
    }
}

// ---------------------------------------------------------------- compact
__global__ void compact_kernel() {
    int row = blockIdx.x * blockDim.x + threadIdx.x;
    bool flag = false;
    if (row < NROWS)
        flag = __uint_as_float(g_mind2[row]) < THRESH;
    unsigned int ball = __ballot_sync(0xffffffffu, flag);
    int lane = threadIdx.x & 31;
    if (ball != 0) {
        int base = 0;
        if (lane == 0) base = atomicAdd(&g_nflag, __popc(ball));
        base = __shfl_sync(0xffffffffu, base, 0);
        if (flag) {
            int off = __popc(ball & ((1u << lane) - 1u));
            g_flagged[base + off] = row;
        }
    }
}

// ---------------------------------------------------------------- exact fallback
__global__ void exact_kernel(const float* __restrict__ o1,
                             const float* __restrict__ o2,
                             const int* __restrict__ rn,
                             const int* __restrict__ quant_p) {
    __shared__ float qv[DDIM];
    __shared__ unsigned long long sred[256];
    __shared__ float svals[1024];
    __shared__ int   sidx[1024];
    int tid = threadIdx.x;

    int nflag = g_nflag;
    if (nflag == 0) return;

    int quant = quant_p ? quant_p[0] : 100;
    int q = quant < (NROWS - 1) ? quant : (NROWS - 1);
    if (q > 1024) q = 1024;
    if (q < 1) q = 1;

    for (int fi = blockIdx.x; fi < nflag; fi += gridDim.x) {
        int row = g_flagged[fi];

        if (tid < DDIM) qv[tid] = o1[row * DDIM + tid];
        __syncthreads();

        unsigned long long* keys = g_scratch[blockIdx.x];
        float s1 = g_sq1[row];
        for (int j = tid; j < NROWS; j += 256) {
            float dot = 0.0f;
            #pragma unroll 8
            for (int d = 0; d < DDIM; d++) dot = fmaf(qv[d], o2[j * DDIM + d], dot);
            float d2 = fmaxf(fmaf(-2.0f, dot, s1 + g_sq2[j]), 0.0f);
            keys[j] = ((unsigned long long)__float_as_uint(d2) << 32) |
                      (unsigned long long)(unsigned)j;
        }
        __syncthreads();

        for (int kk = 0; kk < q; kk++) {
            unsigned long long best = ~0ULL;
            for (int j = tid; j < NROWS; j += 256) {
                unsigned long long v = keys[j];
                if (v < best) best = v;
            }
            sred[tid] = best;
            __syncthreads();
            for (int s = 128; s > 0; s >>= 1) {
                if (tid < s && sred[tid + s] < sred[tid]) sred[tid] = sred[tid + s];
                __syncthreads();
            }
            if (tid == 0) {
                unsigned long long b = sred[0];
                int bj = (int)(unsigned)(b & 0xFFFFFFFFULL);
                float d2 = __uint_as_float((unsigned)(b >> 32));
                svals[kk] = (d2 > 0.0f) ? sqrtf(d2) : 0.0f;
                sidx[kk]  = bj;
                keys[bj] = ~0ULL;
            }
            __syncthreads();
        }

        if (tid == 0) {
            int k = rn[row];
            k = ((k % q) + q) % q;
            if (sidx[k] == row) k = (k + 1) % q;
            float neg = MARGIN_V - svals[k];
            g_neg[row] = neg > 0.0f ? neg : 0.0f;
        }
        __syncthreads();
    }
}

// ---------------------------------------------------------------- finalize
__global__ void finalize_kernel(float* __restrict__ out) {
    __shared__ float s[256];
    int tid = threadIdx.x;
    const float4* p4 = (const float4*)g_pos;
    const float4* n4 = (const float4*)g_neg;
    float acc = 0.0f;
    for (int i = tid; i < NROWS / 4; i += 256) {
        float4 p = p4[i];
        float4 n = n4[i];
        acc += ((p.x + p.y) + (p.z + p.w)) + ((n.x + n.y) + (n.z + n.w));
    }
    s[tid] = acc;
    __syncthreads();
    for (int off = 128; off > 0; off >>= 1) {
        if (tid < off) s[tid] += s[tid + off];
        __syncthreads();
    }
    if (tid == 0) out[0] = s[0] / (float)NROWS;
}

// ---------------------------------------------------------------- launch
extern "C" void kernel_launch(void* const* d_in, const int* in_sizes, int n_in,
                              void* d_out, int out_size) {
    const float* o1 = (const float*)d_in[0];
    const float* o2 = (const float*)d_in[1];
    const int* rn   = (const int*)d_in[2];
    const int* quant = (n_in >= 4) ? (const int*)d_in[3] : nullptr;
    float* out = (float*)d_out;

    norms_kernel<<<NROWS / 8, 256>>>(o1, o2);
    screen_kernel<<<dim3(NROWS / TR, NCTA_COL), 256>>>();
    compact_kernel<<<NROWS / 256, 256>>>();
    exact_kernel<<<64, 256>>>(o1, o2, rn, quant);
    finalize_kernel<<<1, 256>>>(out);
}